// round 1
// baseline (speedup 1.0000x reference)
#include <cuda_runtime.h>
#include <math.h>

// Problem constants
#define IC   32          // in capsules
#define DDIM 288         // ich*w*h = 8*6*6
#define OC   10          // out capsules
#define CH   16          // out channels
#define BSZ  64          // batch
#define JDIM 160         // OC*CH
#define NT   10240       // BSZ*OC*CH
#define NBLK 40          // reduction blocks

// Scratch (device globals: no allocation allowed)
__device__ float g_usum[IC * NT];      // [i][o][b][c]  flat: i*10240 + o*1024 + b*16 + c
__device__ float g_udot[IC * OC];      // [i][o]
__device__ float g_part[3][NBLK];      // per-iteration block partials of L1 norm

// ---------------------------------------------------------------------------
// K1: u_sum[b,i,o,c] = sum_d u[b,i,d] * W[i,d,o,c]
// grid = 32 i * 5 j-chunks(32 wide) = 160 blocks, 256 threads
// also emits complete u_dot[i, 2jc], u_dot[i, 2jc+1] per block (deterministic)
// ---------------------------------------------------------------------------
__global__ __launch_bounds__(256) void k1_gemm(const float* __restrict__ u,
                                               const float* __restrict__ W) {
    const int i  = blockIdx.x / 5;
    const int jc = blockIdx.x % 5;
    const int j0 = jc * 32;
    const int tid = threadIdx.x;
    const int ty = tid >> 4;   // 0..15 -> b = ty*4 + bb
    const int tx = tid & 15;   // 0..15 -> j = j0 + tx*2 + jj

    __shared__ float u_s[96][68];   // [d][b] transposed, padded (68*4B = 16B-aligned rows)
    __shared__ float w_s[96][32];   // [d][jj]
    __shared__ float red[256];

    float a00 = 0.f, a01 = 0.f, a10 = 0.f, a11 = 0.f;
    float a20 = 0.f, a21 = 0.f, a30 = 0.f, a31 = 0.f;

    const float* ub = u + i * DDIM;                       // + b*(IC*DDIM) + d
    const float* wb = W + (size_t)i * DDIM * JDIM + j0;   // + d*JDIM + jj

    for (int d0 = 0; d0 < DDIM; d0 += 96) {
        // load u chunk [64 b][96 d] transposed into smem (global reads coalesced over d)
        for (int k = tid; k < 64 * 96; k += 256) {
            int b = k / 96, dd = k - b * 96;
            u_s[dd][b] = ub[b * (IC * DDIM) + d0 + dd];
        }
        // load W chunk [96 d][32 j]
        for (int k = tid; k < 96 * 32; k += 256) {
            int dd = k >> 5, jj = k & 31;
            w_s[dd][jj] = wb[(d0 + dd) * JDIM + jj];
        }
        __syncthreads();

#pragma unroll 4
        for (int dd = 0; dd < 96; dd++) {
            float4 av = *(const float4*)&u_s[dd][ty * 4];
            float2 wv = *(const float2*)&w_s[dd][tx * 2];
            a00 = fmaf(av.x, wv.x, a00); a01 = fmaf(av.x, wv.y, a01);
            a10 = fmaf(av.y, wv.x, a10); a11 = fmaf(av.y, wv.y, a11);
            a20 = fmaf(av.z, wv.x, a20); a21 = fmaf(av.z, wv.y, a21);
            a30 = fmaf(av.w, wv.x, a30); a31 = fmaf(av.w, wv.y, a31);
        }
        __syncthreads();
    }

    // Store u_sum tile and accumulate u_dot contribution
    float accs[4][2] = {{a00, a01}, {a10, a11}, {a20, a21}, {a30, a31}};
    float lsum = 0.f;
#pragma unroll
    for (int bb = 0; bb < 4; bb++) {
#pragma unroll
        for (int jj = 0; jj < 2; jj++) {
            int j = j0 + tx * 2 + jj;
            int o = j >> 4, c = j & 15;
            int b = ty * 4 + bb;
            g_usum[((i * OC + o) * BSZ + b) * CH + c] = accs[bb][jj];
            lsum += accs[bb][jj];
        }
    }
    red[tid] = lsum;
    __syncthreads();
    // Both of this thread's j values live in the same o (tx<8 -> o=2jc, else 2jc+1).
    // Serial deterministic reduction by two threads.
    if (tid < 2) {
        float s = 0.f;
        for (int k = 0; k < 256; k++) {
            if ((((k & 15) >= 8) ? 1 : 0) == tid) s += red[k];
        }
        g_udot[i * OC + 2 * jc + tid] = s;
    }
}

// ---------------------------------------------------------------------------
// block L1 reduction helper
// ---------------------------------------------------------------------------
__device__ __forceinline__ void block_abs_reduce(float v, float* red, float* dst) {
    red[threadIdx.x] = fabsf(v);
    __syncthreads();
    for (int off = 128; off > 0; off >>= 1) {
        if (threadIdx.x < off) red[threadIdx.x] += red[threadIdx.x + off];
        __syncthreads();
    }
    if (threadIdx.x == 0) dst[blockIdx.x] = red[0];
}

// ---------------------------------------------------------------------------
// K2: iteration 1. c = 1/32 uniform. s1 = (1/32) * sum_i u_sum. n1 partials.
// ---------------------------------------------------------------------------
__global__ __launch_bounds__(256) void k2_iter1() {
    __shared__ float red[256];
    int t = blockIdx.x * 256 + threadIdx.x;
    float s = 0.f;
#pragma unroll
    for (int i = 0; i < IC; i++) s += g_usum[i * NT + t];
    s *= (1.f / 32.f);
    block_abs_reduce(s, red, g_part[0]);
}

// ---------------------------------------------------------------------------
// coupling prologue: fills ud[320], cc[320] = c_{iter} (iter = 2 or 3)
// b_t[i,o] = u_dot[i,o] * g_t[o] (rank-1 recurrence); cc = softmax over i.
// ---------------------------------------------------------------------------
__device__ __forceinline__ void compute_coupling(float* ud, float* cc, int iter) {
    int tid = threadIdx.x;
    for (int k = tid; k < IC * OC; k += blockDim.x) ud[k] = g_udot[k];
    __syncthreads();
    if (tid < OC) {
        int o = tid;
        float n1 = 0.f;
        for (int k = 0; k < NBLK; k++) n1 += g_part[0][k];
        float f1 = n1 / (1.f + n1 * n1);
        float S1 = 0.f;
        for (int q = 0; q < IC; q++) S1 += ud[q * OC + o];
        S1 *= (1.f / 32.f);
        float g = f1 * S1;                       // b2 = ud * g
        if (iter == 3) {
            // c2 from b2, then S2 = sum_i c2*ud, then b3 = ud*(g + f2*S2)
            float m = -1e30f;
            for (int q = 0; q < IC; q++) m = fmaxf(m, ud[q * OC + o] * g);
            float ssum = 0.f;
            for (int q = 0; q < IC; q++) ssum += expf(ud[q * OC + o] * g - m);
            float S2 = 0.f;
            for (int q = 0; q < IC; q++)
                S2 += (expf(ud[q * OC + o] * g - m) / ssum) * ud[q * OC + o];
            float n2 = 0.f;
            for (int k = 0; k < NBLK; k++) n2 += g_part[1][k];
            float f2 = n2 / (1.f + n2 * n2);
            g = g + f2 * S2;                     // b3 = ud * g
        }
        // softmax over i of ud[:,o]*g
        float m = -1e30f;
        for (int q = 0; q < IC; q++) m = fmaxf(m, ud[q * OC + o] * g);
        float ssum = 0.f;
        for (int q = 0; q < IC; q++) {
            float e = expf(ud[q * OC + o] * g - m);
            cc[q * OC + o] = e;
            ssum += e;
        }
        float inv = 1.f / ssum;
        for (int q = 0; q < IC; q++) cc[q * OC + o] *= inv;
    }
    __syncthreads();
}

// ---------------------------------------------------------------------------
// K3: iteration 2. s2 = sum_i c2[i,o]*u_sum ; n2 partials.
// ---------------------------------------------------------------------------
__global__ __launch_bounds__(256) void k3_iter2() {
    __shared__ float ud[IC * OC], cc[IC * OC], red[256];
    compute_coupling(ud, cc, 2);
    int t = blockIdx.x * 256 + threadIdx.x;
    int o = t >> 10;
    float s = 0.f;
#pragma unroll
    for (int i = 0; i < IC; i++) s = fmaf(cc[i * OC + o], g_usum[i * NT + t], s);
    block_abs_reduce(s, red, g_part[1]);
}

// ---------------------------------------------------------------------------
// K4: iteration 3. s3 -> d_out (unscaled) ; n3 partials.
// ---------------------------------------------------------------------------
__global__ __launch_bounds__(256) void k4_iter3(float* __restrict__ out) {
    __shared__ float ud[IC * OC], cc[IC * OC], red[256];
    compute_coupling(ud, cc, 3);
    int t = blockIdx.x * 256 + threadIdx.x;
    int o = t >> 10;
    int b = (t >> 4) & 63;
    int c = t & 15;
    float s = 0.f;
#pragma unroll
    for (int i = 0; i < IC; i++) s = fmaf(cc[i * OC + o], g_usum[i * NT + t], s);
    out[(b * OC + o) * CH + c] = s;   // v (pre-squash-scale)
    block_abs_reduce(s, red, g_part[2]);
}

// ---------------------------------------------------------------------------
// K5: out *= n3 / (1 + n3^2)
// ---------------------------------------------------------------------------
__global__ __launch_bounds__(256) void k5_scale(float* __restrict__ out) {
    __shared__ float fsh;
    if (threadIdx.x == 0) {
        float n3 = 0.f;
        for (int k = 0; k < NBLK; k++) n3 += g_part[2][k];
        fsh = n3 / (1.f + n3 * n3);
    }
    __syncthreads();
    int t = blockIdx.x * 256 + threadIdx.x;
    out[t] *= fsh;
}

// ---------------------------------------------------------------------------
extern "C" void kernel_launch(void* const* d_in, const int* in_sizes, int n_in,
                              void* d_out, int out_size) {
    const float* u = (const float*)d_in[0];   // [64,32,8,6,6]
    const float* W = (const float*)d_in[1];   // [32,8,6,6,10,16]
    float* out = (float*)d_out;               // [64,10,16]
    (void)in_sizes; (void)n_in; (void)out_size;

    k1_gemm<<<160, 256>>>(u, W);
    k2_iter1<<<NBLK, 256>>>();
    k3_iter2<<<NBLK, 256>>>();
    k4_iter3<<<NBLK, 256>>>(out);
    k5_scale<<<NBLK, 256>>>(out);
}